// round 15
// baseline (speedup 1.0000x reference)
#include <cuda_runtime.h>

// Shapes (this instance): B=2048, L=196, M=16, NBL=10. Derived from in_sizes.
#define MAXSITES 256
#define MAXPAIRS 128
#define QTILE_B 4096                    // fused pair tile: 256 float4
#define NSLOT   4
#define WRING_B (NSLOT * QTILE_B)       // 16 KB per-warp ring
#define RING_B  (2 * WRING_B)           // 2 warps per block
#define VSTRIDE 18                      // float2 per chain row (144B)
#define SV_B    (2 * 8 * VSTRIDE * 8)   // 2304 B (2 bufs x 8 chains)
#define SLR_B   512                     // 2 dirs x 4 samples x 16 floats

typedef unsigned long long ull;

// Fused pair tensors (R11-validated):
//  g_QL[p] half0[(m*8+q)] = {P00[m][q],P00[m][q+8],P01[m][q],P01[m][q+8]}
//          half1 = {P10...,P11...};  P_ij = A_i[2p] @ A_j[2p+1]
//  g_QR[p]: right pair p, transposed; P_ij = A_i[Lm2-2-2p] @ A_j[Lm2-1-2p]
__device__ float4 g_QL[MAXPAIRS * 256];
__device__ float4 g_QR[MAXPAIRS * 256];
// Single-site column packs (odd-tail steps):
__device__ float4 g_mat4L[MAXSITES * 128];
__device__ float4 g_mat4R[MAXSITES * 128];

// ---------------------------------------------------------------------------
__device__ __forceinline__ ull pack2(float x, float y) {
    ull r; asm("mov.b64 %0, {%1,%2};" : "=l"(r) : "f"(x), "f"(y)); return r;
}
__device__ __forceinline__ void unpack2(ull v, float& x, float& y) {
    asm("mov.b64 {%0,%1}, %2;" : "=f"(x), "=f"(y) : "l"(v));
}
__device__ __forceinline__ void fma2(ull& d, ull a, ull b) {
    asm("fma.rn.f32x2 %0, %1, %2, %0;" : "+l"(d) : "l"(a), "l"(b));
}
__device__ __forceinline__ ull mul2(ull a, ull b) {
    ull d; asm("mul.rn.f32x2 %0, %1, %2;" : "=l"(d) : "l"(a), "l"(b)); return d;
}
__device__ __forceinline__ void cpasyncCA(unsigned dst, const void* src) {
    asm volatile("cp.async.ca.shared.global [%0], [%1], 16;\n"
                 :: "r"(dst), "l"(src) : "memory");
}
__device__ __forceinline__ void cpcommit() {
    asm volatile("cp.async.commit_group;\n" ::: "memory");
}
template<int N> __device__ __forceinline__ void cpwait() {
    asm volatile("cp.async.wait_group %0;\n" :: "n"(N) : "memory");
}

// ---------------------------------------------------------------------------
// Kernel 1: prep (unchanged from R14). One site-pair job per block, 256 thr.
// ---------------------------------------------------------------------------
__global__ void __launch_bounds__(256)
prep_kernel(const float* __restrict__ A_mid, int Lm2) {
    __shared__ __align__(16) float sF[512];
    __shared__ __align__(16) float sS[512];
    int t = threadIdx.x;
    int PL = Lm2 >> 1;
    bool right = (blockIdx.x >= (unsigned)PL);
    int p = right ? blockIdx.x - PL : blockIdx.x;
    int sFirst  = right ? (Lm2 - 2 - 2 * p) : (2 * p);
    int sSecond = right ? (Lm2 - 1 - 2 * p) : (2 * p + 1);

    if (t < 128)
        ((float4*)sF)[t] = __ldg((const float4*)(A_mid + sFirst * 512) + t);
    else
        ((float4*)sS)[t - 128] = __ldg((const float4*)(A_mid + sSecond * 512) + (t - 128));
    __syncthreads();

    if (!right) {
        int site = 2 * p + (t >> 7);
        const float* S = (t < 128) ? sF : sS;
        int e = t & 127;
        int m = e >> 3, qq = e & 7;
        g_mat4L[site * 128 + e] =
            make_float4(S[m * 16 + qq], S[m * 16 + qq + 8],
                        S[256 + m * 16 + qq], S[256 + m * 16 + qq + 8]);
        g_mat4R[(Lm2 - 1 - site) * 128 + e] =
            make_float4(S[qq * 16 + m], S[(qq + 8) * 16 + m],
                        S[256 + qq * 16 + m], S[256 + (qq + 8) * 16 + m]);
        if (p == 0 && (Lm2 & 1) && t < 128) {
            int s2 = Lm2 - 1;
            const float* A0 = A_mid + s2 * 512;
            const float* A1 = A0 + 256;
            g_mat4L[s2 * 128 + t] =
                make_float4(A0[m * 16 + qq], A0[m * 16 + qq + 8],
                            A1[m * 16 + qq], A1[m * 16 + qq + 8]);
            g_mat4R[(Lm2 - 1 - s2) * 128 + t] =
                make_float4(A0[qq * 16 + m], A0[(qq + 8) * 16 + m],
                            A1[qq * 16 + m], A1[(qq + 8) * 16 + m]);
        }
    }

    int h   = t >> 7;
    int idx = t & 127;
    int m = idx >> 3, qq = idx & 7;
    int rA0 = right ? qq       : m;
    int rA1 = right ? (qq + 8) : m;
    int cB0 = right ? m        : qq;
    int cB1 = right ? m        : (qq + 8);
    const float* F = sF + h * 256;
    float o0 = 0.f, o1 = 0.f, o2 = 0.f, o3 = 0.f;
#pragma unroll
    for (int k = 0; k < 16; ++k) {
        float fa = F[rA0 * 16 + k], fb = F[rA1 * 16 + k];
        float s0a = sS[k * 16 + cB0],       s0b = sS[k * 16 + cB1];
        float s1a = sS[256 + k * 16 + cB0], s1b = sS[256 + k * 16 + cB1];
        o0 = fmaf(fa, s0a, o0);  o1 = fmaf(fb, s0b, o1);
        o2 = fmaf(fa, s1a, o2);  o3 = fmaf(fb, s1b, o3);
    }
    float4* dst = (right ? g_QR : g_QL) + p * 256;
    dst[h * 128 + idx] = make_float4(o0, o1, o2, o3);
}

// ---------------------------------------------------------------------------
// Kernel 2: chains + fused combine. C=4 chains/warp (1 chain per lane-group):
// 1024 warps total (2x R14) for latency hiding.
// Block = 64 thr = 4 samples. Warp 0: LEFT, warp 1: RIGHT (same samples).
// Lane: q = lane&7 owns components {q,q+8}; ch = lane>>3 picks the sample.
// Per-warp 4-slot cp.async.ca ring (2 steps slack), one __syncwarp per step.
// ---------------------------------------------------------------------------
__global__ void __launch_bounds__(64, 3)
chain_kernel(const float* __restrict__ inputs,
             const float* __restrict__ A_left,
             const float* __restrict__ A_right,
             const float* __restrict__ T,
             const int*   __restrict__ pos_ptr,
             float* __restrict__ out,
             int B, int L, int NBL) {
    extern __shared__ __align__(16) char smem[];
    const int Lm2 = L - 2;
    char*   ring = smem;                                 // RING_B
    float2* sVs  = (float2*)(smem + RING_B);             // SV_B
    float*  sLR  = (float*)(smem + RING_B + SV_B);       // SLR_B

    int tid  = threadIdx.x;
    int w    = tid >> 5;                                 // 0 = left, 1 = right
    int lane = tid & 31;
    int q    = lane & 7;
    int ch   = lane >> 3;                                // 0..3 sample

    const float2* in2 = (const float2*)inputs;           // (B,L) float2

    int pos = __ldg(pos_ptr);
    bool isLeft = (w == 0);
    int cidx = w * 4 + ch;                               // chain slot 0..7
    int c    = blockIdx.x * 4 + ch;                      // global sample
    int nsites = isLeft ? pos : (Lm2 - pos);
    int P = nsites >> 1;
    const float* seedA = isLeft ? A_left : A_right;
    int seedX = isLeft ? 0 : (L - 1);

    float sa0 = __ldg(seedA + q),     sa1 = __ldg(seedA + 16 + q);
    float sb0 = __ldg(seedA + q + 8), sb1 = __ldg(seedA + 16 + q + 8);
    float2 xs = __ldg(in2 + c * L + seedX);
    float v0 = fmaf(xs.y, sa1, xs.x * sa0);
    float v1 = fmaf(xs.y, sb1, xs.x * sb0);
    {   // seed splats -> buffer 0
        float2* d = sVs + cidx * VSTRIDE;
        d[q] = make_float2(v0, v0); d[q + 8] = make_float2(v1, v1);
    }

    const float4* QT = isLeft ? g_QL : g_QR;
    unsigned ringW = (unsigned)__cvta_generic_to_shared(ring) + w * WRING_B;

    auto stage = [&](int p, int slot) {
        if (p < P) {
            const float4* src = QT + p * 256;
            unsigned dst = ringW + slot * QTILE_B;
#pragma unroll
            for (int kk = 0; kk < 8; ++kk) {
                int chunk = lane + kk * 32;
                cpasyncCA(dst + chunk * 16, src + chunk);
            }
        }
        cpcommit();
    };

    auto make_coef = [&](float2 xi, float2 xj, ull* cc) {
        cc[0] = pack2(xi.x * xj.x, xi.x * xj.x);
        cc[1] = pack2(xi.x * xj.y, xi.x * xj.y);
        cc[2] = pack2(xi.y * xj.x, xi.y * xj.x);
        cc[3] = pack2(xi.y * xj.y, xi.y * xj.y);
    };

    auto do_step = [&](int t, int slot, const ull* cc) {
        const char* tile = ring + w * WRING_B + slot * QTILE_B;
        int vb = t & 1;
        ull vv[16];
        {
            const ulonglong2* pa =
                (const ulonglong2*)(sVs + vb * 8 * VSTRIDE + cidx * VSTRIDE);
#pragma unroll
            for (int j = 0; j < 8; ++j) {
                ulonglong2 ta = pa[j]; vv[2 * j] = ta.x; vv[2 * j + 1] = ta.y;
            }
        }
        ull a0=0ull,a1=0ull,a2=0ull,a3=0ull;
#pragma unroll
        for (int m = 0; m < 16; ++m) {
            ulonglong2 M0 = *(const ulonglong2*)(tile + (m * 8 + q) * 16);
            ulonglong2 M1 = *(const ulonglong2*)(tile + 2048 + (m * 8 + q) * 16);
            fma2(a0, vv[m], M0.x); fma2(a1, vv[m], M0.y);
            fma2(a2, vv[m], M1.x); fma2(a3, vv[m], M1.y);
        }
        ull r0 = mul2(cc[0], a0); fma2(r0, cc[1], a1);
        ull r1 = mul2(cc[2], a2); fma2(r1, cc[3], a3);
        ull r; asm("add.rn.f32x2 %0, %1, %2;" : "=l"(r) : "l"(r0), "l"(r1));
        unpack2(r, v0, v1);

        float2* d = sVs + (1 - vb) * 8 * VSTRIDE + cidx * VSTRIDE;
        d[q] = make_float2(v0, v0); d[q + 8] = make_float2(v1, v1);
    };

    // ---- warp-autonomous main loop: 4-slot ring, 2 steps of slack ------------
    stage(0, 0); stage(1, 1); stage(2, 2);

    ull cc[4];
    if (P > 0) {
        int siteI = isLeft ? 1 : (L - 3);
        int siteJ = isLeft ? 2 : (L - 2);
        make_coef(__ldg(in2 + c * L + siteI), __ldg(in2 + c * L + siteJ), cc);
    }
    int slotCur = 0, slotPre = 3;
    for (int t = 0; t < P; ++t) {
        float2 nxi, nxj;
        bool more = (t + 1 < P);
        if (more) {
            int siteI = isLeft ? (3 + 2 * t) : (L - 5 - 2 * t);
            int siteJ = isLeft ? (4 + 2 * t) : (L - 4 - 2 * t);
            nxi = __ldg(in2 + c * L + siteI);
            nxj = __ldg(in2 + c * L + siteJ);
        }
        cpwait<2>();
        __syncwarp();                       // publish cp.async data + prev v STS
        stage(t + 3, slotPre);
        do_step(t, slotCur, cc);
        if (more) make_coef(nxi, nxj, cc);
        slotCur = (slotCur == NSLOT - 1) ? 0 : slotCur + 1;
        slotPre = (slotPre == NSLOT - 1) ? 0 : slotPre + 1;
    }
    cpwait<0>();
    __syncwarp();

    // ---- odd tail: one single-site step straight from L2 ---------------------
    if (nsites & 1) {
        int vb = P & 1;
        ull vv[16];
        {
            const ulonglong2* pa =
                (const ulonglong2*)(sVs + vb * 8 * VSTRIDE + cidx * VSTRIDE);
#pragma unroll
            for (int j = 0; j < 8; ++j) {
                ulonglong2 ta = pa[j]; vv[2 * j] = ta.x; vv[2 * j + 1] = ta.y;
            }
        }
        int s = 2 * P;
        const float4* mat = (isLeft ? g_mat4L : g_mat4R) + s * 128;
        int xin = isLeft ? (1 + s) : (L - 2 - s);
        float2 xA = __ldg(in2 + c * L + xin);
        ull a0 = 0ull, a1 = 0ull;
#pragma unroll
        for (int m = 0; m < 16; ++m) {
            float4 Mf = __ldg(mat + m * 8 + q);
            fma2(a0, vv[m], pack2(Mf.x, Mf.y));
            fma2(a1, vv[m], pack2(Mf.z, Mf.w));
        }
        ull r = mul2(pack2(xA.x, xA.x), a0);
        fma2(r, pack2(xA.y, xA.y), a1);
        unpack2(r, v0, v1);
    }

    // ---- publish chain results, fused combine ---------------------------------
    float* sL = sLR;
    float* sR = sLR + 64;
    {
        float* d = (isLeft ? sL : sR) + ch * 16;
        d[q] = v0; d[q + 8] = v1;
    }
    __syncthreads();

    float* sT = (float*)ring;
    int tElems = 256 * NBL;
    for (int i = tid; i < tElems; i += 64) sT[i] = __ldg(T + i);
    __syncthreads();

    int total = 4 * NBL;
    if (tid < total) {
        int b = tid / NBL, l = tid - b * NBL;
        float acc = 0.f;
#pragma unroll
        for (int m = 0; m < 16; ++m) {
            float t2 = 0.f;
#pragma unroll
            for (int k = 0; k < 16; ++k)
                t2 = fmaf(sT[(m * 16 + k) * NBL + l], sR[b * 16 + k], t2);
            acc = fmaf(sL[b * 16 + m], t2, acc);
        }
        out[(blockIdx.x * 4 + b) * NBL + l] = acc;
    }
}

// ---------------------------------------------------------------------------
extern "C" void kernel_launch(void* const* d_in, const int* in_sizes, int n_in,
                              void* d_out, int out_size) {
    const float* inputs  = (const float*)d_in[0];
    const float* A_left  = (const float*)d_in[1];
    const float* A_mid   = (const float*)d_in[2];
    const float* A_right = (const float*)d_in[3];
    const float* T_out   = (const float*)d_in[4];
    const int*   pos     = (const int*)d_in[5];

    int Lm2 = in_sizes[2] / 512;          // L-2 = 194
    int L   = Lm2 + 2;                    // 196
    int B   = in_sizes[0] / (2 * L);      // 2048
    int NBL = in_sizes[4] / 256;          // 10

    int PL = Lm2 >> 1;                    // 97
    prep_kernel<<<2 * PL, 256>>>(A_mid, Lm2);

    int nblocks = B / 4;                  // 512 blocks (1024 warps)
    size_t smemB = (size_t)RING_B + SV_B + SLR_B;   // ~35.6 KB

    cudaFuncSetAttribute(chain_kernel,
                         cudaFuncAttributeMaxDynamicSharedMemorySize,
                         (int)smemB);
    chain_kernel<<<nblocks, 64, smemB>>>(inputs, A_left, A_right,
                                         T_out, pos, (float*)d_out,
                                         B, L, NBL);
}